// round 17
// baseline (speedup 1.0000x reference)
#include <cuda_runtime.h>
#include <cuda_fp16.h>

#define NI 2000      // inner tree nodes
#define NL 10000     // leaves / vocab
#define ND 128       // docs
#define PP 2048      // padded proj width
#define FC 64        // mass feature chunk
#define NMASS_CH 157 // ceil(NL/FC)
#define AG_BLKS 400  // argmax: 10 float4-col blocks x 40 row-chunks
#define AG_CH 50     // rows per argmax chunk
#define AG_RB 10     // load batch (MLP)
#define MP_BLKS (3 * NMASS_CH)   // 471 mass-pair blocks (now in k_mix)
#define SROWH 68     // half2 row stride per feature-pair
// proj scatter: 2 leaf-slices per doc
#define SC_BLKS (2 * ND)          // 256
#define SL4 1250                  // float4-leaves per slice
// proj-pair: 32-doc tiles, 64-f chunks, 2x2 micro (verified config)
#define PT 32
#define PSROW 36
#define NPP 10
#define PP_BLKS (NPP * (PP / FC))   // 320
#define MIX_BLKS (MP_BLKS + PP_BLKS + (ND * ND) / 256)   // 855

__device__ unsigned long long g_amax[NL];
__device__ float g_proj[ND * PP];
__device__ float g_S[ND];

__constant__ int c_it[NPP] = {0,0,0,0,1,1,1,2,2,3};
__constant__ int c_jt[NPP] = {0,1,2,3,1,2,3,2,3,3};

__device__ __forceinline__ __half2 u2h2(unsigned u) {
    return *reinterpret_cast<__half2*>(&u);
}
__device__ __forceinline__ unsigned long long pack_key(float v, int idx) {
    unsigned u = __float_as_uint(v);
    u = (u & 0x80000000u) ? ~u : (u | 0x80000000u);
    return ((unsigned long long)u << 32) | (unsigned)idx;
}
__device__ __forceinline__ void red4(float* p, float4 v) {
    asm volatile("red.global.add.v4.f32 [%0], {%1,%2,%3,%4};"
                 :: "l"(p), "f"(v.x), "f"(v.y), "f"(v.z), "f"(v.w) : "memory");
}

// ---------------------------------------------------------------- init
__global__ void k_init(float* __restrict__ out) {
    int i = blockIdx.x * blockDim.x + threadIdx.x;
    if (i < ND * PP) g_proj[i] = 0.0f;
    if (i < NL) g_amax[i] = 0ull;
    if (i < ND * ND) out[i] = 0.0f;
    if (i < ND) g_S[i] = 0.0f;
}

// ---------------------------------------------------------------- pure argmax (PDL: scan pre-sync, atomics post-sync)
__global__ void __launch_bounds__(256)
k_argmax(const float* __restrict__ param) {
    int bid = blockIdx.x;
    int tid = threadIdx.x;
    int j4 = (bid % 10) * 256 + tid;
    bool ok = j4 < NL / 4;
    int j4c = ok ? j4 : (NL / 4 - 1);
    int r0 = (bid / 10) * AG_CH;
    const float4* p = (const float4*)param + (size_t)r0 * (NL / 4) + j4c;
    float4 bv = make_float4(-3.4e38f, -3.4e38f, -3.4e38f, -3.4e38f);
    int ix = r0, iy = r0, iz = r0, iw = r0;
    for (int rb = 0; rb < AG_CH; rb += AG_RB) {
        float4 v[AG_RB];
        #pragma unroll
        for (int k = 0; k < AG_RB; k++)
            v[k] = p[(size_t)(rb + k) * (NL / 4)];
        #pragma unroll
        for (int k = 0; k < AG_RB; k++) {
            int r = r0 + rb + k;
            if (v[k].x > bv.x) { bv.x = v[k].x; ix = r; }
            if (v[k].y > bv.y) { bv.y = v[k].y; iy = r; }
            if (v[k].z > bv.z) { bv.z = v[k].z; iz = r; }
            if (v[k].w > bv.w) { bv.w = v[k].w; iw = r; }
        }
    }
    cudaGridDependencySynchronize();   // wait: init zeroed g_amax
    if (ok) {
        int j = 4 * j4;
        atomicMax(&g_amax[j + 0], pack_key(bv.x, ix));
        atomicMax(&g_amax[j + 1], pack_key(bv.y, iy));
        atomicMax(&g_amax[j + 2], pack_key(bv.z, iz));
        atomicMax(&g_amax[j + 3], pack_key(bv.w, iw));
    }
}

// ---------------------------------------------------------------- proj: 2 slices/doc, scatter + tree-sum + REDG merge
__global__ void __launch_bounds__(256)
k_proj(const float* __restrict__ mass) {
    __shared__ float s[NI];
    __shared__ float red[256];
    int tid = threadIdx.x;
    int d = blockIdx.x >> 1;
    int sl = blockIdx.x & 1;
    for (int i = tid; i < NI; i += 256) s[i] = 0.0f;
    cudaGridDependencySynchronize();   // wait: argmax wrote g_amax
    __syncthreads();
    const float4* m4 = (const float4*)(mass + (size_t)d * NL);
    int base = sl * SL4;
    for (int j4 = base + tid; j4 < base + SL4; j4 += 256) {
        float4 v = m4[j4];
        int a0 = (int)(unsigned)(__ldg(&g_amax[4 * j4 + 0]) & 0xFFFFFFFFull);
        int a1 = (int)(unsigned)(__ldg(&g_amax[4 * j4 + 1]) & 0xFFFFFFFFull);
        int a2 = (int)(unsigned)(__ldg(&g_amax[4 * j4 + 2]) & 0xFFFFFFFFull);
        int a3 = (int)(unsigned)(__ldg(&g_amax[4 * j4 + 3]) & 0xFFFFFFFFull);
        atomicAdd(&s[a0], v.x);
        atomicAdd(&s[a1], v.y);
        atomicAdd(&s[a2], v.z);
        atomicAdd(&s[a3], v.w);
    }
    __syncthreads();
    const int lo[5] = {156, 31, 6, 1, 0};
    const int hi[5] = {399, 155, 30, 5, 0};
    for (int L = 0; L < 5; L++) {
        for (int p = lo[L] + tid; p <= hi[L]; p += 256) {
            float acc = s[p];
            int c0 = 5 * p + 1;
            #pragma unroll
            for (int c = 0; c < 5; c++)
                if (c0 + c < NI) acc += s[c0 + c];
            s[p] = acc;
        }
        __syncthreads();
    }
    float psum = 0.0f;
    float* gp = g_proj + (size_t)d * PP;
    for (int i = tid * 4; i < NI; i += 1024) {
        float4 a = *(float4*)&s[i];
        psum += a.x + a.y + a.z + a.w;
        red4(&gp[i], a);
    }
    red[tid] = psum;
    __syncthreads();
    for (int w = 128; w > 0; w >>= 1) {
        if (tid < w) red[tid] += red[tid + w];
        __syncthreads();
    }
    if (tid == 0) atomicAdd(&g_S[d], red[0]);
}

// ---------------------------------------------------------------- mix: masspair (no sync) || projpair + S epilogue (sync)
__global__ void __launch_bounds__(256)
k_mix(const float* __restrict__ mass, float* __restrict__ out) {
    __shared__ union {
        __half2 mp[2][32 * SROWH];
        struct { float sa[FC * PSROW]; float sb[FC * PSROW]; } pp;
    } sm;
    int tid = threadIdx.x;

    if (blockIdx.x < MP_BLKS) {
        // ---- fp16 mass-pair: independent of proj; runs during k_proj via PDL ----
        int pid = blockIdx.x;             // 0..470
        int tp = pid % 3;                 // 0:(0,0) 1:(0,1)+mirror 2:(1,1)
        int chunk = pid / 3;
        int fb = chunk * FC;
        int nh = min(FC, NL - fb) >> 1;
        int it = (tp == 2) ? 1 : 0;
        int jt = (tp == 0) ? 0 : 1;
        __half2* sa2 = sm.mp[0];
        __half2* sb2 = sm.mp[1];

        const __half2 hz = __float2half2_rn(0.0f);
        #pragma unroll
        for (int k = 0; k < 8; k++) {
            int idx = tid + k * 256;          // 0..2047
            int f2 = idx & 31;
            int row = idx >> 5;               // 0..63
            __half2 ha = hz, hb = hz;
            if (f2 < nh) {
                float2 va = *(const float2*)&mass[(size_t)(it * 64 + row) * NL + fb + 2 * f2];
                float2 vb = *(const float2*)&mass[(size_t)(jt * 64 + row) * NL + fb + 2 * f2];
                ha = __floats2half2_rn(va.x, va.y);
                hb = __floats2half2_rn(vb.x, vb.y);
            }
            sa2[f2 * SROWH + row] = ha;
            sb2[f2 * SROWH + row] = hb;
        }
        __syncthreads();

        int tx = tid & 15, ty = tid >> 4;
        __half2 acc[4][4];
        #pragma unroll
        for (int r = 0; r < 4; r++)
            #pragma unroll
            for (int c = 0; c < 4; c++) acc[r][c] = hz;

        #pragma unroll 4
        for (int f2 = 0; f2 < 32; f2++) {
            uint4 ua = *(const uint4*)&sa2[f2 * SROWH + ty * 4];
            uint4 ub = *(const uint4*)&sb2[f2 * SROWH + tx * 4];
            __half2 ar[4] = {u2h2(ua.x), u2h2(ua.y), u2h2(ua.z), u2h2(ua.w)};
            __half2 br[4] = {u2h2(ub.x), u2h2(ub.y), u2h2(ub.z), u2h2(ub.w)};
            #pragma unroll
            for (int r = 0; r < 4; r++)
                #pragma unroll
                for (int c = 0; c < 4; c++)
                    acc[r][c] = __hadd2(acc[r][c], __hmin2(ar[r], br[c]));
        }

        int ib = it * 64 + ty * 4, jb = jt * 64 + tx * 4;
        #pragma unroll
        for (int r = 0; r < 4; r++)
            #pragma unroll
            for (int c = 0; c < 4; c++) {
                float2 f = __half22float2(acc[r][c]);
                float v = -2.0f * (f.x + f.y);
                atomicAdd(&out[(ib + r) * ND + (jb + c)], v);
                if (tp == 1)
                    atomicAdd(&out[(jb + c) * ND + (ib + r)], v);
            }
    } else if (blockIdx.x < MP_BLKS + PP_BLKS) {
        // ---- fp32 proj-pair: needs g_proj complete ----
        cudaGridDependencySynchronize();   // wait: k_proj done
        int pid = blockIdx.x - MP_BLKS;
        int tp = pid % NPP;
        int fb = (pid / NPP) * FC;
        int it = c_it[tp], jt = c_jt[tp];
        float* sa = sm.pp.sa;
        float* sb = sm.pp.sb;

        #pragma unroll
        for (int k = 0; k < 8; k++) {
            int idx = tid + k * 256;          // 0..2047 = 64 f x 32 rows
            int f = idx & 63;
            int row = idx >> 6;               // 0..31
            sa[f * PSROW + row] = g_proj[(size_t)(it * PT + row) * PP + fb + f];
            sb[f * PSROW + row] = g_proj[(size_t)(jt * PT + row) * PP + fb + f];
        }
        __syncthreads();

        int tx = tid & 15, ty = tid >> 4;
        float acc[2][2] = {{0.f, 0.f}, {0.f, 0.f}};
        #pragma unroll 8
        for (int f = 0; f < FC; f++) {
            float2 a = *(const float2*)&sa[f * PSROW + ty * 2];
            float2 b = *(const float2*)&sb[f * PSROW + tx * 2];
            acc[0][0] += fminf(a.x, b.x);
            acc[0][1] += fminf(a.x, b.y);
            acc[1][0] += fminf(a.y, b.x);
            acc[1][1] += fminf(a.y, b.y);
        }

        int ib = it * PT + ty * 2, jb = jt * PT + tx * 2;
        #pragma unroll
        for (int r = 0; r < 2; r++)
            #pragma unroll
            for (int c = 0; c < 2; c++) {
                float v = -2.0f * acc[r][c];
                atomicAdd(&out[(ib + r) * ND + (jb + c)], v);
                if (it != jt)
                    atomicAdd(&out[(jb + c) * ND + (ib + r)], v);
            }
    } else {
        // ---- S epilogue: needs g_S complete ----
        cudaGridDependencySynchronize();
        int e = (blockIdx.x - MP_BLKS - PP_BLKS) * 256 + tid;  // 0..16383
        // +2.0f = sum(mass_i) + sum(mass_j) (each doc's mass sums to 1)
        atomicAdd(&out[e], g_S[e >> 7] + g_S[e & 127] + 2.0f);
    }
}

// ---------------------------------------------------------------- launch (PDL chain)
extern "C" void kernel_launch(void* const* d_in, const int* in_sizes, int n_in,
                              void* d_out, int out_size) {
    const float* mass  = (const float*)d_in[0];   // (128, 10000) f32
    const float* param = (const float*)d_in[1];   // (2000, 10000) f32
    float* out = (float*)d_out;                   // (128, 128) f32

    k_init<<<1024, 256>>>(out);

    cudaLaunchConfig_t cfg = {};
    cfg.blockDim = {256, 1, 1};
    cfg.stream = 0;
    cudaLaunchAttribute attr;
    attr.id = cudaLaunchAttributeProgrammaticStreamSerialization;
    attr.val.programmaticStreamSerializationAllowed = 1;
    cfg.attrs = &attr;
    cfg.numAttrs = 1;

    cfg.gridDim = {AG_BLKS, 1, 1};
    cudaLaunchKernelEx(&cfg, k_argmax, param);

    cfg.gridDim = {SC_BLKS, 1, 1};
    cudaLaunchKernelEx(&cfg, k_proj, mass);

    cfg.gridDim = {MIX_BLKS, 1, 1};
    cudaLaunchKernelEx(&cfg, k_mix, mass, out);
}